// round 8
// baseline (speedup 1.0000x reference)
#include <cuda_runtime.h>
#include <math.h>

#define V 720
#define U 736
#define NXY 512
#define NTAPS 368

#define DU_D   1.2858
#define DSO_D  595.0
#define DOD_D  490.6
#define DSD_D  (DSO_D + DOD_D)
#define SVOX_D 400.0
#define PI_D   3.14159265358979323846

// parity-packed conv arrays
#define PADE 380
#define PODD 383
#define WLEN 1124

// guard-band padded filtered rows: slot i holds detector index u = i - QPAD
#define QPAD 512
#define QSTRIDE 1760            // 512 + 736 + 512

// ---- device-global scratch ----
__device__ float4 g_trig[V];          // (cb*DSD/DU, sb*DSD/DU, cb, sb)
__device__ float2 g_Qp[V * QSTRIDE];  // (Q[u], Q[u+1]-Q[u]); (0,0) outside [0,U-2]

// ---------------------------------------------------------------------------
// Kernel 1: cosine weight + Ram-Lak conv (parity-packed, register-tiled),
// one block (192 thr) per view. Writes trig table + padded (q, dq) rows.
// ---------------------------------------------------------------------------
__global__ __launch_bounds__(192) void filter_kernel(const float* __restrict__ sino) {
    __shared__ __align__(16) float wo_s[WLEN];
    __shared__ __align__(16) float we_s[WLEN];
    __shared__ __align__(16) float ho_s[NTAPS];
    __shared__ float qrow[U];

    const int v = blockIdx.x;
    const int tid = threadIdx.x;

    for (int i = tid; i < WLEN; i += 192) { wo_s[i] = 0.0f; we_s[i] = 0.0f; }
    for (int k = tid; k < NTAPS; k += 192) {
        float d = (float)(PI_D * DU_D) * (float)(2 * k + 1);
        ho_s[k] = -1.0f / (d * d);
    }
    if (tid == 0) {
        float bf = (float)(2.0 * PI_D * (double)v / (double)V);
        float cb = (float)cos((double)bf);
        float sb = (float)sin((double)bf);
        float kk = (float)(DSD_D / DU_D);
        g_trig[v] = make_float4(cb * kk, sb * kk, cb, sb);
    }
    __syncthreads();

    {
        const float* row = sino + v * U;
        const float dsd  = (float)DSD_D;
        const float dsd2 = (float)(DSD_D * DSD_D);
        const float du   = (float)DU_D;
        for (int u = tid; u < U; u += 192) {
            float us = ((float)u - 367.5f) * du;
            float w = row[u] * (dsd * rsqrtf(dsd2 + us * us));
            if (u & 1) wo_s[PADE + (u >> 1)] = w;
            else       we_s[PODD + (u >> 1)] = w;
        }
    }
    __syncthreads();

    const int grp = tid / 96;
    const int t   = tid % 96;
    if (t < 92) {
        const int b = 4 * t;
        const float* A = grp ? (we_s + PODD + 1) : (wo_s + PADE);
        const float* C = grp ? (wo_s + PADE)     : (we_s + PODD);
        const float h0 = (float)(1.0 / (4.0 * DU_D * DU_D));

        float acc0 = h0 * C[b + 0];
        float acc1 = h0 * C[b + 1];
        float acc2 = h0 * C[b + 2];
        float acc3 = h0 * C[b + 3];

        float4 Llo = *(const float4*)(A + b - 4);
        float4 Lhi = *(const float4*)(A + b);
        float4 rlo = *(const float4*)(A + b);
        float4 rhi = *(const float4*)(A + b + 4);

        #pragma unroll 4
        for (int j = 0; j < 92; j++) {
            float4 h4 = *(const float4*)(ho_s + 4 * j);
            acc0 += h4.x * (Llo.w + rlo.x);
            acc1 += h4.x * (Lhi.x + rlo.y);
            acc2 += h4.x * (Lhi.y + rlo.z);
            acc3 += h4.x * (Lhi.z + rlo.w);
            acc0 += h4.y * (Llo.z + rlo.y);
            acc1 += h4.y * (Llo.w + rlo.z);
            acc2 += h4.y * (Lhi.x + rlo.w);
            acc3 += h4.y * (Lhi.y + rhi.x);
            acc0 += h4.z * (Llo.y + rlo.z);
            acc1 += h4.z * (Llo.z + rlo.w);
            acc2 += h4.z * (Llo.w + rhi.x);
            acc3 += h4.z * (Lhi.x + rhi.y);
            acc0 += h4.w * (Llo.x + rlo.w);
            acc1 += h4.w * (Llo.y + rhi.x);
            acc2 += h4.w * (Llo.z + rhi.y);
            acc3 += h4.w * (Llo.w + rhi.z);
            Lhi = Llo;
            Llo = *(const float4*)(A + b - 4 * j - 8);
            rlo = rhi;
            rhi = *(const float4*)(A + b + 4 * j + 8);
        }

        const float du = (float)DU_D;
        const int u0 = 8 * t + grp;
        qrow[u0 + 0] = du * acc0;
        qrow[u0 + 2] = du * acc1;
        qrow[u0 + 4] = du * acc2;
        qrow[u0 + 6] = du * acc3;
    }
    __syncthreads();

    // padded (q, dq) pairs: slot i <-> u = i - QPAD.
    // EXACT reference masking: any slot outside [0, U-2] is (0,0).
    {
        float2* dst = g_Qp + v * QSTRIDE;
        for (int i = tid; i < QSTRIDE; i += 192) {
            int s = i - QPAD;
            bool in = (s >= 0) && (s <= U - 2);
            float q0 = in ? qrow[s] : 0.0f;
            float q1 = in ? qrow[s + 1] : 0.0f;
            dst[i] = make_float2(q0, q1 - q0);
        }
    }
}

// ---------------------------------------------------------------------------
// Kernel 2: weighted fan-beam backprojection.
// Block (32,8): iy = bx*32+tx, pixels ix0 = by*16+ty and ix0+8.
// 2-view x 2-pixel unroll. Guard-banded Q (no clamps/predicates) +
// RD-magic floor: no F2I/I2F anywhere in the loop.
// ---------------------------------------------------------------------------
#define M23 8388608.0f                       // 2^23
#define ADDR_BIAS 0x258000000ULL             // 0x4B000000 * sizeof(float2)

__global__ __launch_bounds__(256, 4) void bp_kernel(float* __restrict__ out) {
    __shared__ __align__(16) float4 strig[V];

    const int tid = threadIdx.y * 32 + threadIdx.x;
    for (int i = tid; i < V; i += 256) strig[i] = g_trig[i];
    __syncthreads();

    const int iy  = blockIdx.x * 32 + threadIdx.x;
    const int ix0 = blockIdx.y * 16 + threadIdx.y;   // second pixel: ix0 + 8

    const float dx   = (float)(SVOX_D / (double)NXY);
    const float y    = ((float)iy  - 255.5f) * dx;
    const float x0   = ((float)ix0 - 255.5f) * dx;
    const float stp  = 8.0f * dx;
    const float c0   = 367.5f + (float)QPAD;         // guard shift folded in
    const float dso  = (float)DSO_D;

    // bias-adjusted base so addr = m_bits * 8 + base (single IMAD.WIDE)
    unsigned long long pa = (unsigned long long)(const char*)g_Qp - ADDR_BIAS;
    const unsigned long long rowB = (unsigned long long)QSTRIDE * 8ULL;

    float accA0 = 0.0f, accA1 = 0.0f, accB0 = 0.0f, accB1 = 0.0f;

    #pragma unroll 2
    for (int v = 0; v < V; v += 2, pa += 2ULL * rowB) {
        float4 ta = strig[v];
        float4 tb = strig[v + 1];

        float tA0 = fmaf(x0, ta.x, y * ta.y);
        float tA1 = fmaf(stp, ta.x, tA0);
        float DA0 = fmaf(x0, ta.w, fmaf(-y, ta.z, dso));
        float DA1 = fmaf(stp, ta.w, DA0);
        float tB0 = fmaf(x0, tb.x, y * tb.y);
        float tB1 = fmaf(stp, tb.x, tB0);
        float DB0 = fmaf(x0, tb.w, fmaf(-y, tb.z, dso));
        float DB1 = fmaf(stp, tb.w, DB0);

        float rA0, rA1, rB0, rB1;
        asm("rcp.approx.f32 %0, %1;" : "=f"(rA0) : "f"(DA0));
        asm("rcp.approx.f32 %0, %1;" : "=f"(rA1) : "f"(DA1));
        asm("rcp.approx.f32 %0, %1;" : "=f"(rB0) : "f"(DB0));
        asm("rcp.approx.f32 %0, %1;" : "=f"(rB1) : "f"(DB1));

        float iA0 = fmaf(tA0, rA0, c0);
        float iA1 = fmaf(tA1, rA1, c0);
        float iB0 = fmaf(tB0, rB0, c0);
        float iB1 = fmaf(tB1, rB1, c0);

        // RD-magic floor: mantissa(m) == floor(idx); no F2I/I2F.
        float mA0 = __fadd_rd(iA0, M23);
        float mA1 = __fadd_rd(iA1, M23);
        float mB0 = __fadd_rd(iB0, M23);
        float mB1 = __fadd_rd(iB1, M23);

        float2 qA0 = __ldg((const float2*)(pa + (unsigned long long)__float_as_uint(mA0) * 8ULL));
        float2 qA1 = __ldg((const float2*)(pa + (unsigned long long)__float_as_uint(mA1) * 8ULL));
        float2 qB0 = __ldg((const float2*)(pa + rowB + (unsigned long long)__float_as_uint(mB0) * 8ULL));
        float2 qB1 = __ldg((const float2*)(pa + rowB + (unsigned long long)__float_as_uint(mB1) * 8ULL));

        // exact fraction: fl = m - 2^23 (exact), f = idx - fl (Sterbenz-exact)
        float fA0 = iA0 - (mA0 - M23);
        float fA1 = iA1 - (mA1 - M23);
        float fB0 = iB0 - (mB0 - M23);
        float fB1 = iB1 - (mB1 - M23);

        float vA0 = fmaf(fA0, qA0.y, qA0.x);
        float vA1 = fmaf(fA1, qA1.y, qA1.x);
        float vB0 = fmaf(fB0, qB0.y, qB0.x);
        float vB1 = fmaf(fB1, qB1.y, qB1.x);

        accA0 = fmaf(vA0, rA0 * rA0, accA0);
        accA1 = fmaf(vA1, rA1 * rA1, accA1);
        accB0 = fmaf(vB0, rB0 * rB0, accB0);
        accB1 = fmaf(vB1, rB1 * rB1, accB1);
    }

    const float scale = (float)(0.5 * (2.0 * PI_D / (double)V) * DSO_D * DSO_D);
    out[ix0 * NXY + iy]       = (accA0 + accB0) * scale;
    out[(ix0 + 8) * NXY + iy] = (accA1 + accB1) * scale;
}

// ---------------------------------------------------------------------------
extern "C" void kernel_launch(void* const* d_in, const int* in_sizes, int n_in,
                              void* d_out, int out_size) {
    (void)in_sizes; (void)n_in; (void)out_size;
    const float* sino = (const float*)d_in[0];
    float* out = (float*)d_out;

    filter_kernel<<<V, 192>>>(sino);
    dim3 bpBlock(32, 8);
    dim3 bpGrid(NXY / 32, NXY / 16);   // 16 x 32 = 512 blocks
    bp_kernel<<<bpGrid, bpBlock>>>(out);
}

// round 9
// speedup vs baseline: 1.4426x; 1.4426x over previous
#include <cuda_runtime.h>
#include <math.h>

#define V 720
#define HV 360
#define U 736
#define NXY 512
#define NPIX (NXY * NXY)
#define NTAPS 368

#define DU_D   1.2858
#define DSO_D  595.0
#define DOD_D  490.6
#define DSD_D  (DSO_D + DOD_D)
#define SVOX_D 400.0
#define PI_D   3.14159265358979323846

// parity-packed conv arrays
#define PADE 380
#define PODD 383
#define WLEN 1124

// guard-band padded filtered rows: slot i holds detector index u = i - QPAD
#define QPAD 512
#define QSTRIDE 1760            // 512 + 736 + 512

// ---- device-global scratch ----
__device__ float4 g_trig[V];          // (cb*DSD/DU, sb*DSD/DU, cb, sb)
__device__ float2 g_Qp[V * QSTRIDE];  // (Q[u], Q[u+1]-Q[u]); (0,0) outside [0,U-2]
__device__ float  g_accS[NPIX];       // self partial (views 0..359)
__device__ float  g_accN[NPIX];       // partner partial (goes to mirrored pixel)

// ---------------------------------------------------------------------------
// Kernel 1: cosine weight + Ram-Lak conv (parity-packed, register-tiled),
// one block (192 thr) per view. Writes trig table + padded (q, dq) rows.
// ---------------------------------------------------------------------------
__global__ __launch_bounds__(192) void filter_kernel(const float* __restrict__ sino) {
    __shared__ __align__(16) float wo_s[WLEN];
    __shared__ __align__(16) float we_s[WLEN];
    __shared__ __align__(16) float ho_s[NTAPS];
    __shared__ float qrow[U];

    const int v = blockIdx.x;
    const int tid = threadIdx.x;

    for (int i = tid; i < WLEN; i += 192) { wo_s[i] = 0.0f; we_s[i] = 0.0f; }
    for (int k = tid; k < NTAPS; k += 192) {
        float d = (float)(PI_D * DU_D) * (float)(2 * k + 1);
        ho_s[k] = -1.0f / (d * d);
    }
    if (tid == 0) {
        float bf = (float)(2.0 * PI_D * (double)v / (double)V);
        float cb = (float)cos((double)bf);
        float sb = (float)sin((double)bf);
        float kk = (float)(DSD_D / DU_D);
        g_trig[v] = make_float4(cb * kk, sb * kk, cb, sb);
    }
    __syncthreads();

    {
        const float* row = sino + v * U;
        const float dsd  = (float)DSD_D;
        const float dsd2 = (float)(DSD_D * DSD_D);
        const float du   = (float)DU_D;
        for (int u = tid; u < U; u += 192) {
            float us = ((float)u - 367.5f) * du;
            float w = row[u] * (dsd * rsqrtf(dsd2 + us * us));
            if (u & 1) wo_s[PADE + (u >> 1)] = w;
            else       we_s[PODD + (u >> 1)] = w;
        }
    }
    __syncthreads();

    const int grp = tid / 96;
    const int t   = tid % 96;
    if (t < 92) {
        const int b = 4 * t;
        const float* A = grp ? (we_s + PODD + 1) : (wo_s + PADE);
        const float* C = grp ? (wo_s + PADE)     : (we_s + PODD);
        const float h0 = (float)(1.0 / (4.0 * DU_D * DU_D));

        float acc0 = h0 * C[b + 0];
        float acc1 = h0 * C[b + 1];
        float acc2 = h0 * C[b + 2];
        float acc3 = h0 * C[b + 3];

        float4 Llo = *(const float4*)(A + b - 4);
        float4 Lhi = *(const float4*)(A + b);
        float4 rlo = *(const float4*)(A + b);
        float4 rhi = *(const float4*)(A + b + 4);

        #pragma unroll 4
        for (int j = 0; j < 92; j++) {
            float4 h4 = *(const float4*)(ho_s + 4 * j);
            acc0 += h4.x * (Llo.w + rlo.x);
            acc1 += h4.x * (Lhi.x + rlo.y);
            acc2 += h4.x * (Lhi.y + rlo.z);
            acc3 += h4.x * (Lhi.z + rlo.w);
            acc0 += h4.y * (Llo.z + rlo.y);
            acc1 += h4.y * (Llo.w + rlo.z);
            acc2 += h4.y * (Lhi.x + rlo.w);
            acc3 += h4.y * (Lhi.y + rhi.x);
            acc0 += h4.z * (Llo.y + rlo.z);
            acc1 += h4.z * (Llo.z + rlo.w);
            acc2 += h4.z * (Llo.w + rhi.x);
            acc3 += h4.z * (Lhi.x + rhi.y);
            acc0 += h4.w * (Llo.x + rlo.w);
            acc1 += h4.w * (Llo.y + rhi.x);
            acc2 += h4.w * (Llo.z + rhi.y);
            acc3 += h4.w * (Llo.w + rhi.z);
            Lhi = Llo;
            Llo = *(const float4*)(A + b - 4 * j - 8);
            rlo = rhi;
            rhi = *(const float4*)(A + b + 4 * j + 8);
        }

        const float du = (float)DU_D;
        const int u0 = 8 * t + grp;
        qrow[u0 + 0] = du * acc0;
        qrow[u0 + 2] = du * acc1;
        qrow[u0 + 4] = du * acc2;
        qrow[u0 + 6] = du * acc3;
    }
    __syncthreads();

    // padded (q, dq) pairs: slot i <-> u = i - QPAD.
    // EXACT reference masking: any slot outside [0, U-2] is (0,0).
    {
        float2* dst = g_Qp + v * QSTRIDE;
        for (int i = tid; i < QSTRIDE; i += 192) {
            int s = i - QPAD;
            bool in = (s >= 0) && (s <= U - 2);
            float q0 = in ? qrow[s] : 0.0f;
            float q1 = in ? qrow[s + 1] : 0.0f;
            dst[i] = make_float2(q0, q1 - q0);
        }
    }
}

// ---------------------------------------------------------------------------
// Kernel 2: symmetric backprojection over views 0..359 only.
// For pixel P at view v, geometry (u, w) is IDENTICAL to pixel -P at view
// v+360 (cos/sin negate). Each geometry eval feeds accS (P <- Q[v]) and
// accN (-P <- Q[v+360], same slot, constant +360-row byte offset).
// Block (32,8): iy = bx*32+tx, pixels ix0 = by*8+ty and ix0+256.
// ---------------------------------------------------------------------------
#define M23 8388608.0f                       // 2^23
#define ADDR_BIAS 0x258000000ULL             // 0x4B000000 * sizeof(float2)
#define ROWB ((unsigned long long)QSTRIDE * 8ULL)
#define ROW360B (360ULL * ROWB)              // 5,068,800 (fits LDG imm)

__global__ __launch_bounds__(256, 4) void bp_kernel() {
    __shared__ __align__(16) float4 strig[HV];

    const int tid = threadIdx.y * 32 + threadIdx.x;
    for (int i = tid; i < HV; i += 256) strig[i] = g_trig[i];
    __syncthreads();

    const int iy  = blockIdx.x * 32 + threadIdx.x;
    const int ix0 = blockIdx.y * 8 + threadIdx.y;    // second pixel: ix0 + 256

    const float dx   = (float)(SVOX_D / (double)NXY);
    const float y    = ((float)iy  - 255.5f) * dx;
    const float x0   = ((float)ix0 - 255.5f) * dx;
    const float stp  = 256.0f * dx;
    const float c0   = 367.5f + (float)QPAD;
    const float dso  = (float)DSO_D;

    unsigned long long pa = (unsigned long long)(const char*)g_Qp - ADDR_BIAS;

    float accS0 = 0.0f, accS1 = 0.0f, accN0 = 0.0f, accN1 = 0.0f;

    #pragma unroll 4
    for (int v = 0; v < HV; v++, pa += ROWB) {
        float4 tg = strig[v];

        float t0 = fmaf(x0, tg.x, y * tg.y);
        float t1 = fmaf(stp, tg.x, t0);
        float D0 = fmaf(x0, tg.w, fmaf(-y, tg.z, dso));
        float D1 = fmaf(stp, tg.w, D0);

        float r0, r1;
        asm("rcp.approx.f32 %0, %1;" : "=f"(r0) : "f"(D0));
        asm("rcp.approx.f32 %0, %1;" : "=f"(r1) : "f"(D1));

        float i0 = fmaf(t0, r0, c0);
        float i1 = fmaf(t1, r1, c0);

        float m0 = __fadd_rd(i0, M23);
        float m1 = __fadd_rd(i1, M23);

        unsigned long long a0 = pa + (unsigned long long)__float_as_uint(m0) * 8ULL;
        unsigned long long a1 = pa + (unsigned long long)__float_as_uint(m1) * 8ULL;

        float2 q0s = __ldg((const float2*)a0);
        float2 q0n = __ldg((const float2*)(a0 + ROW360B));
        float2 q1s = __ldg((const float2*)a1);
        float2 q1n = __ldg((const float2*)(a1 + ROW360B));

        float f0 = i0 - (m0 - M23);
        float f1 = i1 - (m1 - M23);

        float w0 = r0 * r0;
        float w1 = r1 * r1;

        accS0 = fmaf(fmaf(f0, q0s.y, q0s.x), w0, accS0);
        accN0 = fmaf(fmaf(f0, q0n.y, q0n.x), w0, accN0);
        accS1 = fmaf(fmaf(f1, q1s.y, q1s.x), w1, accS1);
        accN1 = fmaf(fmaf(f1, q1n.y, q1n.x), w1, accN1);
    }

    g_accS[ix0 * NXY + iy]          = accS0;
    g_accS[(ix0 + 256) * NXY + iy]  = accS1;
    g_accN[ix0 * NXY + iy]          = accN0;
    g_accN[(ix0 + 256) * NXY + iy]  = accN1;
}

// ---------------------------------------------------------------------------
// Kernel 3: combine. out[i] = scale*(S[i] + N[mirror(i)]), mirror(i)=NPIX-1-i
// (pixel negation (ix,iy)->(511-ix,511-iy) is exactly index reversal).
// ---------------------------------------------------------------------------
__global__ __launch_bounds__(256) void combine_kernel(float* __restrict__ out) {
    const int i = blockIdx.x * 256 + threadIdx.x;
    const float scale = (float)(0.5 * (2.0 * PI_D / (double)V) * DSO_D * DSO_D);
    out[i] = (g_accS[i] + g_accN[NPIX - 1 - i]) * scale;
}

// ---------------------------------------------------------------------------
extern "C" void kernel_launch(void* const* d_in, const int* in_sizes, int n_in,
                              void* d_out, int out_size) {
    (void)in_sizes; (void)n_in; (void)out_size;
    const float* sino = (const float*)d_in[0];
    float* out = (float*)d_out;

    filter_kernel<<<V, 192>>>(sino);
    dim3 bpBlock(32, 8);
    dim3 bpGrid(NXY / 32, 32);          // 16 x 32 = 512 blocks
    bp_kernel<<<bpGrid, bpBlock>>>();
    combine_kernel<<<NPIX / 256, 256>>>(out);
}

// round 11
// speedup vs baseline: 1.8241x; 1.2645x over previous
#include <cuda_runtime.h>
#include <math.h>

#define V 720
#define QV 180
#define U 736
#define NXY 512
#define NPIX (NXY * NXY)
#define NTAPS 368

#define DU_D   1.2858
#define DSO_D  595.0
#define DOD_D  490.6
#define DSD_D  (DSO_D + DOD_D)
#define SVOX_D 400.0
#define PI_D   3.14159265358979323846

// parity-packed conv arrays
#define PADE 380
#define PODD 383
#define WLEN 1124

// guard-band padded filtered rows: slot i holds detector index u = i - QPAD
#define QPAD 512
#define QSTRIDE 1760            // 512 + 736 + 512

// ---- device-global scratch ----
__device__ float4 g_trig[V];          // (cb*DSD/DU, sb*DSD/DU, cb, sb)
__device__ float2 g_Qp[V * QSTRIDE];  // (Q[u], Q[u+1]-Q[u]); (0,0) outside [0,U-2]
__device__ float  g_accS[NPIX];       // views   0..179 -> pixel P
__device__ float  g_acc90[NPIX];      // views 180..359 -> rot90(P)
__device__ float  g_acc180[NPIX];     // views 360..539 -> -P
__device__ float  g_acc270[NPIX];     // views 540..719 -> rot270(P)

// ---------------------------------------------------------------------------
// Kernel 1: cosine weight + Ram-Lak conv (parity-packed, register-tiled),
// one block (192 thr) per view. Writes trig table + padded (q, dq) rows.
// ---------------------------------------------------------------------------
__global__ __launch_bounds__(192) void filter_kernel(const float* __restrict__ sino) {
    __shared__ __align__(16) float wo_s[WLEN];
    __shared__ __align__(16) float we_s[WLEN];
    __shared__ __align__(16) float ho_s[NTAPS];
    __shared__ float qrow[U];

    const int v = blockIdx.x;
    const int tid = threadIdx.x;

    for (int i = tid; i < WLEN; i += 192) { wo_s[i] = 0.0f; we_s[i] = 0.0f; }
    for (int k = tid; k < NTAPS; k += 192) {
        float d = (float)(PI_D * DU_D) * (float)(2 * k + 1);
        ho_s[k] = -1.0f / (d * d);
    }
    if (tid == 0) {
        float bf = (float)(2.0 * PI_D * (double)v / (double)V);
        float cb = (float)cos((double)bf);
        float sb = (float)sin((double)bf);
        float kk = (float)(DSD_D / DU_D);
        g_trig[v] = make_float4(cb * kk, sb * kk, cb, sb);
    }
    __syncthreads();

    {
        const float* row = sino + v * U;
        const float dsd  = (float)DSD_D;
        const float dsd2 = (float)(DSD_D * DSD_D);
        const float du   = (float)DU_D;
        for (int u = tid; u < U; u += 192) {
            float us = ((float)u - 367.5f) * du;
            float w = row[u] * (dsd * rsqrtf(dsd2 + us * us));
            if (u & 1) wo_s[PADE + (u >> 1)] = w;
            else       we_s[PODD + (u >> 1)] = w;
        }
    }
    __syncthreads();

    const int grp = tid / 96;
    const int t   = tid % 96;
    if (t < 92) {
        const int b = 4 * t;
        const float* A = grp ? (we_s + PODD + 1) : (wo_s + PADE);
        const float* C = grp ? (wo_s + PADE)     : (we_s + PODD);
        const float h0 = (float)(1.0 / (4.0 * DU_D * DU_D));

        float acc0 = h0 * C[b + 0];
        float acc1 = h0 * C[b + 1];
        float acc2 = h0 * C[b + 2];
        float acc3 = h0 * C[b + 3];

        float4 Llo = *(const float4*)(A + b - 4);
        float4 Lhi = *(const float4*)(A + b);
        float4 rlo = *(const float4*)(A + b);
        float4 rhi = *(const float4*)(A + b + 4);

        #pragma unroll 4
        for (int j = 0; j < 92; j++) {
            float4 h4 = *(const float4*)(ho_s + 4 * j);
            acc0 += h4.x * (Llo.w + rlo.x);
            acc1 += h4.x * (Lhi.x + rlo.y);
            acc2 += h4.x * (Lhi.y + rlo.z);
            acc3 += h4.x * (Lhi.z + rlo.w);
            acc0 += h4.y * (Llo.z + rlo.y);
            acc1 += h4.y * (Llo.w + rlo.z);
            acc2 += h4.y * (Lhi.x + rlo.w);
            acc3 += h4.y * (Lhi.y + rhi.x);
            acc0 += h4.z * (Llo.y + rlo.z);
            acc1 += h4.z * (Llo.z + rlo.w);
            acc2 += h4.z * (Llo.w + rhi.x);
            acc3 += h4.z * (Lhi.x + rhi.y);
            acc0 += h4.w * (Llo.x + rlo.w);
            acc1 += h4.w * (Llo.y + rhi.x);
            acc2 += h4.w * (Llo.z + rhi.y);
            acc3 += h4.w * (Llo.w + rhi.z);
            Lhi = Llo;
            Llo = *(const float4*)(A + b - 4 * j - 8);
            rlo = rhi;
            rhi = *(const float4*)(A + b + 4 * j + 8);
        }

        const float du = (float)DU_D;
        const int u0 = 8 * t + grp;
        qrow[u0 + 0] = du * acc0;
        qrow[u0 + 2] = du * acc1;
        qrow[u0 + 4] = du * acc2;
        qrow[u0 + 6] = du * acc3;
    }
    __syncthreads();

    // padded (q, dq) pairs: slot i <-> u = i - QPAD.
    // EXACT reference masking: any slot outside [0, U-2] is (0,0).
    {
        float2* dst = g_Qp + v * QSTRIDE;
        for (int i = tid; i < QSTRIDE; i += 192) {
            int s = i - QPAD;
            bool in = (s >= 0) && (s <= U - 2);
            float q0 = in ? qrow[s] : 0.0f;
            float q1 = in ? qrow[s + 1] : 0.0f;
            dst[i] = make_float2(q0, q1 - q0);
        }
    }
}

// ---------------------------------------------------------------------------
// Kernel 2: 4-fold symmetric backprojection over views 0..179.
// Geometry (u, w) for (P, v) is bit-identical for (rot90 P, v+180),
// (-P, v+360), (rot270 P, v+540). One eval -> 4 accumulations from
// rows v, v+180, v+360, v+540 (constant byte offsets).
// ---------------------------------------------------------------------------
#define M23 8388608.0f                       // 2^23
#define ADDR_BIAS 0x258000000ULL             // 0x4B000000 * sizeof(float2)
#define ROWB ((unsigned long long)QSTRIDE * 8ULL)
#define R180B (180ULL * ROWB)                // 2,534,400 bytes

__global__ __launch_bounds__(256, 4) void bp_kernel() {
    __shared__ __align__(16) float4 strig[QV];

    const int tid = threadIdx.y * 32 + threadIdx.x;
    for (int i = tid; i < QV; i += 256) strig[i] = g_trig[i];
    __syncthreads();

    const int iy = blockIdx.x * 32 + threadIdx.x;
    const int ix = blockIdx.y * 8 + threadIdx.y;

    const float dx  = (float)(SVOX_D / (double)NXY);
    const float y   = ((float)iy - 255.5f) * dx;
    const float x   = ((float)ix - 255.5f) * dx;
    const float c0  = 367.5f + (float)QPAD;
    const float dso = (float)DSO_D;

    unsigned long long pa = (unsigned long long)(const char*)g_Qp - ADDR_BIAS;

    float accS = 0.0f, acc90 = 0.0f, acc180 = 0.0f, acc270 = 0.0f;

    #pragma unroll 4
    for (int v = 0; v < QV; v++, pa += ROWB) {
        float4 tg = strig[v];

        float t = fmaf(x, tg.x, y * tg.y);
        float D = fmaf(x, tg.w, fmaf(-y, tg.z, dso));
        float r;
        asm("rcp.approx.f32 %0, %1;" : "=f"(r) : "f"(D));
        float idx = fmaf(t, r, c0);
        float m = __fadd_rd(idx, M23);

        unsigned long long a = pa + (unsigned long long)__float_as_uint(m) * 8ULL;
        float2 q0 = __ldg((const float2*)a);
        float2 q1 = __ldg((const float2*)(a + R180B));
        float2 q2 = __ldg((const float2*)(a + 2ULL * R180B));
        float2 q3 = __ldg((const float2*)(a + 3ULL * R180B));

        float f = idx - (m - M23);
        float w = r * r;

        accS   = fmaf(fmaf(f, q0.y, q0.x), w, accS);
        acc90  = fmaf(fmaf(f, q1.y, q1.x), w, acc90);
        acc180 = fmaf(fmaf(f, q2.y, q2.x), w, acc180);
        acc270 = fmaf(fmaf(f, q3.y, q3.x), w, acc270);
    }

    const int p = ix * NXY + iy;
    g_accS[p]   = accS;
    g_acc90[p]  = acc90;
    g_acc180[p] = acc180;
    g_acc270[p] = acc270;
}

// ---------------------------------------------------------------------------
// Kernel 3: combine. For output O=(ix,iy):
//   out[O] = scale * ( S[O] + acc90[rot270(O)] + acc180[-O] + acc270[rot90(O)] )
// rot90(ix,iy)=(511-iy,ix); rot270(ix,iy)=(iy,511-ix); -O = (511-ix,511-iy).
// ---------------------------------------------------------------------------
__global__ __launch_bounds__(256) void combine_kernel(float* __restrict__ out) {
    const int i = blockIdx.x * 256 + threadIdx.x;
    const int ix = i >> 9;
    const int iy = i & 511;
    const float scale = (float)(0.5 * (2.0 * PI_D / (double)V) * DSO_D * DSO_D);

    float s   = g_accS[i];
    float a18 = g_acc180[NPIX - 1 - i];
    float a9  = g_acc90[iy * NXY + (NXY - 1 - ix)];    // P = rot270(O)
    float a27 = g_acc270[(NXY - 1 - iy) * NXY + ix];   // P = rot90(O)

    out[i] = (s + a9 + a18 + a27) * scale;
}

// ---------------------------------------------------------------------------
extern "C" void kernel_launch(void* const* d_in, const int* in_sizes, int n_in,
                              void* d_out, int out_size) {
    (void)in_sizes; (void)n_in; (void)out_size;
    const float* sino = (const float*)d_in[0];
    float* out = (float*)d_out;

    filter_kernel<<<V, 192>>>(sino);
    dim3 bpBlock(32, 8);
    dim3 bpGrid(NXY / 32, NXY / 8);     // 16 x 64 = 1024 blocks
    bp_kernel<<<bpGrid, bpBlock>>>();
    combine_kernel<<<NPIX / 256, 256>>>(out);
}